// round 16
// baseline (speedup 1.0000x reference)
#include <cuda_runtime.h>
#include <cuda_bf16.h>
#include <cstdint>

#define Bv 4
#define Nv 1024
#define Tv (Bv*Nv)   // 4096 tokens

// ---------------- fp32 scratch ----------------
__device__ float g_Yada[Tv*1536];
__device__ float g_Ysig[Tv*768];
__device__ float g_qkvg[Tv*512];
__device__ float g_bsig[768];
__device__ float g_bqkv[3*512];
__device__ float g_zb[3*Bv*32*4*32*128];   // [i][b][j][h][qq][k] pair-bias

// ---------------- split (hi/lo bf16x2-packed) activations ----------------
__device__ uint32_t g_lnc_h[Tv*32], g_lnc_l[Tv*32];
__device__ uint32_t g_c_h[Tv*32],   g_c_l[Tv*32];
__device__ uint32_t g_ah_h[Tv*64],  g_ah_l[Tv*64];
__device__ uint32_t g_tt_h[Tv*64],  g_tt_l[Tv*64];
__device__ uint32_t g_ob_h[Tv*64],  g_ob_l[Tv*64];
__device__ uint32_t g_bm_h[Tv*128], g_bm_l[Tv*128];

// ---------------- split weights [K/2][N] ----------------
__device__ uint32_t g_Wada_h[32*1536], g_Wada_l[32*1536];
__device__ uint32_t g_Wsig_h[32*768],  g_Wsig_l[32*768];
__device__ uint32_t g_Wqkvg_h[3*64*512], g_Wqkvg_l[3*64*512];
__device__ uint32_t g_W12_h[3*64*512],   g_W12_l[3*64*512];
__device__ uint32_t g_Wo_h[3*64*128],    g_Wo_l[3*64*128];
__device__ uint32_t g_Wout_h[3*128*128], g_Wout_l[3*128*128];

__device__ __forceinline__ float sigmoidf_(float x) { return 1.f/(1.f+__expf(-x)); }
__device__ __forceinline__ void pack2_(float x0, float x1, uint32_t& h, uint32_t& l) {
    __nv_bfloat162 hh = __floats2bfloat162_rn(x0, x1);
    float r0 = x0 - __bfloat162float(hh.x);
    float r1 = x1 - __bfloat162float(hh.y);
    __nv_bfloat162 ll = __floats2bfloat162_rn(r0, r1);
    h = *reinterpret_cast<uint32_t*>(&hh);
    l = *reinterpret_cast<uint32_t*>(&ll);
}
__device__ __forceinline__ void cpasync16_(uint32_t dst, const void* src) {
    asm volatile("cp.async.ca.shared.global [%0], [%1], 16;" :: "r"(dst), "l"(src));
}
__device__ __forceinline__ void cpasync16z_(uint32_t dst, const void* src, uint32_t sz) {
    asm volatile("cp.async.ca.shared.global [%0], [%1], 16, %2;" :: "r"(dst), "l"(src), "r"(sz));
}
template<int N> __device__ __forceinline__ void cp_wait_() {
    asm volatile("cp.async.wait_group %0;" :: "n"(N));
}
#define MMAB_(acc, a, b) \
    asm volatile("mma.sync.aligned.m16n8k16.row.col.f32.bf16.bf16.f32 " \
        "{%0,%1,%2,%3}, {%4,%5,%6,%7}, {%8,%9}, {%0,%1,%2,%3};" \
        : "+f"(acc[0]), "+f"(acc[1]), "+f"(acc[2]), "+f"(acc[3]) \
        : "r"(a[0]), "r"(a[1]), "r"(a[2]), "r"(a[3]), "r"(b[0]), "r"(b[1]))

#define PACK_TOTAL (32*1536 + 32*768 + 768 + 3*64*512 + 3*512 + 3*64*512 + 3*64*128 + 3*128*128)
#define PACK_CTAS ((PACK_TOTAL + 255)/256)

// ---------------- head kernel: weight pack/split + ln(c) in one node --------
__global__ void head_kernel(
    const float* __restrict__ c,
    const float* __restrict__ attn_s_gamma, const float* __restrict__ attn_gate_w,
    const float* __restrict__ attn_skip_w,
    const float* __restrict__ trans_s_gamma, const float* __restrict__ trans_gate_w,
    const float* __restrict__ trans_skip_w,
    const float* __restrict__ attn_ws_out, const float* __restrict__ attn_bs_out,
    const float* __restrict__ trans_ws_out, const float* __restrict__ trans_bs_out,
    const float* __restrict__ wq, const float* __restrict__ bq,
    const float* __restrict__ wk, const float* __restrict__ wv,
    const float* __restrict__ wg,
    const float* __restrict__ w1, const float* __restrict__ w2,
    const float* __restrict__ wo, const float* __restrict__ wout)
{
    if (blockIdx.x >= PACK_CTAS) {
        int lane = threadIdx.x & 31;
        int tok = (blockIdx.x - PACK_CTAS)*8 + (threadIdx.x >> 5);
        float2 cv = *(const float2*)&c[(size_t)tok*64 + lane*2];
        float s = cv.x + cv.y, sq = cv.x*cv.x + cv.y*cv.y;
        #pragma unroll
        for (int off = 16; off; off >>= 1) {
            s  += __shfl_xor_sync(0xffffffffu, s,  off);
            sq += __shfl_xor_sync(0xffffffffu, sq, off);
        }
        float m = s * (1.f/64.f);
        float var = sq * (1.f/64.f) - m*m;
        float rs = rsqrtf(var + 1e-5f);
        pack2_((cv.x-m)*rs, (cv.y-m)*rs, g_lnc_h[tok*32+lane], g_lnc_l[tok*32+lane]);
        pack2_(cv.x, cv.y, g_c_h[tok*32+lane], g_c_l[tok*32+lane]);
        return;
    }
    int idx = blockIdx.x*blockDim.x + threadIdx.x;
    const int P0 = 32*1536;
    const int P1 = P0 + 32*768;
    const int P2 = P1 + 768;
    const int P3 = P2 + 3*64*512;
    const int P4 = P3 + 3*512;
    const int P5 = P4 + 3*64*512;
    const int P6 = P5 + 3*64*128;
    const int P7 = P6 + 3*128*128;
    if (idx < P0) {
        int kp = idx/1536, col = idx%1536;
        int i = col>>9, r = col&511, m = r>>7, o = r&127;
        const float* src = (m==0)?attn_gate_w:(m==1)?attn_skip_w:(m==2)?trans_gate_w:trans_skip_w;
        const float* gam = (m<2)?attn_s_gamma:trans_s_gamma;
        float x0 = src[(i*64+2*kp  )*128+o] * gam[i*64+2*kp];
        float x1 = src[(i*64+2*kp+1)*128+o] * gam[i*64+2*kp+1];
        pack2_(x0, x1, g_Wada_h[idx], g_Wada_l[idx]);
    } else if (idx < P1) {
        int l = idx - P0; int kp = l/768, col = l%768;
        int i = col/256, r = col%256, m = r>>7, o = r&127;
        const float* src = m ? trans_ws_out : attn_ws_out;
        pack2_(src[(i*64+2*kp)*128+o], src[(i*64+2*kp+1)*128+o], g_Wsig_h[l], g_Wsig_l[l]);
    } else if (idx < P2) {
        int col = idx - P1;
        int i = col/256, r = col%256, m = r>>7, o = r&127;
        g_bsig[col] = m ? trans_bs_out[i*128+o] : attn_bs_out[i*128+o];
    } else if (idx < P3) {
        int l = idx - P2; int i = l/(64*512); int rem = l%(64*512);
        int kp = rem>>9, col = rem&511, m = col>>7, o = col&127;
        const float* src = (m==0)?wq:(m==1)?wk:(m==2)?wv:wg;
        pack2_(src[(i*128+2*kp)*128+o], src[(i*128+2*kp+1)*128+o], g_Wqkvg_h[l], g_Wqkvg_l[l]);
    } else if (idx < P4) {
        int l = idx - P3; int i = l>>9, col = l&511;
        g_bqkv[l] = (col<128) ? bq[i*128+col] : 0.f;
    } else if (idx < P5) {
        int l = idx - P4; int i = l/(64*512); int rem = l%(64*512);
        int kp = rem>>9, col = rem&511, j = col>>1;
        const float* src = (col&1) ? w2 : w1;
        pack2_(src[(i*128+2*kp)*256+j], src[(i*128+2*kp+1)*256+j], g_W12_h[l], g_W12_l[l]);
    } else if (idx < P6) {
        int l = idx - P5; int i = l/(64*128); int rem = l%(64*128);
        int kp = rem>>7, n = rem&127;
        pack2_(wo[(i*128+2*kp)*128+n], wo[(i*128+2*kp+1)*128+n], g_Wo_h[l], g_Wo_l[l]);
    } else if (idx < P7) {
        int l = idx - P6; int i = l/(128*128); int rem = l%(128*128);
        int kp = rem>>7, n = rem&127;
        pack2_(wout[(i*256+2*kp)*128+n], wout[(i*256+2*kp+1)*128+n], g_Wout_h[l], g_Wout_l[l]);
    }
}

// ---------------- zb precompute ----------------
__global__ void __launch_bounds__(256) zb_kernel(
    const float* __restrict__ p,
    const float* __restrict__ lnz_g, const float* __restrict__ lnz_b,
    const float* __restrict__ wb)
{
    __shared__ float wbp[3][16][4];
    __shared__ float cst[3][4];
    int j = blockIdx.x, b = blockIdx.y;
    int tid = threadIdx.x;
    int k0 = 32*j - 48, q0 = 32*j;
    if (tid < 192) {
        int i = tid/64, r = tid%64, cc = r>>2, h = r&3;
        wbp[i][cc][h] = lnz_g[i*16+cc] * wb[i*64 + cc*4 + h];
    } else if (tid < 204) {
        int t2 = tid-192, i = t2/4, h = t2%4;
        float s = 0.f;
        for (int cc = 0; cc < 16; ++cc) s += lnz_b[i*16+cc]*wb[i*64+cc*4+h];
        cst[i][h] = s;
    }
    __syncthreads();
    size_t base0 = ((size_t)b*32 + j) << 14;
    const size_t islab = (size_t)Bv*32*16384;
    for (int pr = tid; pr < 4096; pr += 256) {
        int qq = pr >> 7, k = pr & 127;
        int gk = k0 + k;
        if (gk < 0 || gk >= Nv) {
            #pragma unroll
            for (int i = 0; i < 3; ++i)
                #pragma unroll
                for (int h = 0; h < 4; ++h)
                    g_zb[i*islab + base0 + h*4096 + qq*128 + k] = 0.f;
            continue;
        }
        const float* pp = p + (((size_t)(b*Nv + q0 + qq))*Nv + gk)*16;
        float vals[16];
        #pragma unroll
        for (int c4 = 0; c4 < 4; ++c4) {
            float4 f = ((const float4*)pp)[c4];
            vals[c4*4+0]=f.x; vals[c4*4+1]=f.y; vals[c4*4+2]=f.z; vals[c4*4+3]=f.w;
        }
        float s = 0.f, sq = 0.f;
        #pragma unroll
        for (int cc = 0; cc < 16; ++cc) { s += vals[cc]; sq += vals[cc]*vals[cc]; }
        float m = s*(1.f/16.f), var = sq*(1.f/16.f) - m*m;
        float rs = rsqrtf(var + 1e-5f);
        #pragma unroll
        for (int cc = 0; cc < 16; ++cc) vals[cc] = (vals[cc]-m)*rs;
        #pragma unroll
        for (int i = 0; i < 3; ++i) {
            #pragma unroll
            for (int h = 0; h < 4; ++h) {
                float z = cst[i][h];
                #pragma unroll
                for (int cc = 0; cc < 16; ++cc) z += vals[cc]*wbp[i][cc][h];
                g_zb[i*islab + base0 + h*4096 + qq*128 + k] = z;
            }
        }
    }
}

// ---------------- adaln (standalone; used only for block 0 from q) ----------
__global__ void adaln_kernel(const float* __restrict__ a_in, int blk)
{
    int lane = threadIdx.x & 31;
    int tok = blockIdx.x*4 + (threadIdx.x >> 5);
    float4 av = *(const float4*)&a_in[(size_t)tok*128 + lane*4];
    float s  = av.x+av.y+av.z+av.w;
    float sq = av.x*av.x+av.y*av.y+av.z*av.z+av.w*av.w;
    #pragma unroll
    for (int off = 16; off; off >>= 1) {
        s  += __shfl_xor_sync(0xffffffffu, s,  off);
        sq += __shfl_xor_sync(0xffffffffu, sq, off);
    }
    float m = s * (1.f/128.f);
    float var = sq * (1.f/128.f) - m*m;
    float rs = rsqrtf(var + 1e-5f);
    const float* yr = g_Yada + (size_t)tok*1536 + blk*512;
    float4 yga = *(const float4*)&yr[lane*4];
    float4 ysk = *(const float4*)&yr[128 + lane*4];
    float4 ygt = *(const float4*)&yr[256 + lane*4];
    float4 yst = *(const float4*)&yr[384 + lane*4];
    float a0=(av.x-m)*rs, a1=(av.y-m)*rs, a2=(av.z-m)*rs, a3=(av.w-m)*rs;
    float ah0 = sigmoidf_(yga.x)*a0 + ysk.x;
    float ah1 = sigmoidf_(yga.y)*a1 + ysk.y;
    float ah2 = sigmoidf_(yga.z)*a2 + ysk.z;
    float ah3 = sigmoidf_(yga.w)*a3 + ysk.w;
    float tt0 = sigmoidf_(ygt.x)*a0 + yst.x;
    float tt1 = sigmoidf_(ygt.y)*a1 + yst.y;
    float tt2 = sigmoidf_(ygt.z)*a2 + yst.z;
    float tt3 = sigmoidf_(ygt.w)*a3 + yst.w;
    int o = tok*64 + lane*2;
    pack2_(ah0, ah1, g_ah_h[o],   g_ah_l[o]);
    pack2_(ah2, ah3, g_ah_h[o+1], g_ah_l[o+1]);
    pack2_(tt0, tt1, g_tt_h[o],   g_tt_l[o]);
    pack2_(tt2, tt3, g_tt_h[o+1], g_tt_l[o+1]);
}

// ------------- split-bf16 tensor GEMM, 128x64 tile, cp.async 2-stage --------
struct GJob {
    const uint32_t *Ah, *Al, *Wh, *Wl;
    const float *bias;
    float *C;
    uint32_t *Ch, *Cl;
    int K, N, act;
};
#define AH0 0
#define AL0 5120
#define BH0 10240
#define BL0 12544
#define BG_SMEM (14848*4)
__global__ void __launch_bounds__(256,2) bgemm_kernel(GJob j0, GJob j1)
{
    GJob jb = (blockIdx.z == 0) ? j0 : j1;
    int n0 = blockIdx.x << 6;
    if (n0 >= jb.N) return;
    int m0 = blockIdx.y << 7;
    extern __shared__ uint32_t smu[];
    uint32_t shBase = (uint32_t)__cvta_generic_to_shared(smu);

    int tid = threadIdx.x, lane = tid & 31, w = tid >> 5;
    int wm = (w & 3) << 5, wn = (w >> 2) << 5;
    int g = lane >> 2, tig = lane & 3;
    int lda = jb.K >> 1;

    float acc[2][4][4];
    #pragma unroll
    for (int mt = 0; mt < 2; ++mt)
        #pragma unroll
        for (int nt = 0; nt < 4; ++nt)
            #pragma unroll
            for (int r = 0; r < 4; ++r) acc[mt][nt][r] = 0.f;

    int ntk = jb.K >> 5;
    auto load_tile = [&](int buf, int t) {
        int kt2 = t << 4;
        #pragma unroll
        for (int l = 0; l < 2; ++l) {
            int idx = tid + (l << 8);
            int row = idx >> 2, kpb = (idx & 3) << 2;
            size_t gsrc = (size_t)(m0 + row)*lda + kt2 + kpb;
            uint32_t d = (buf*2560 + row*20 + kpb) << 2;
            cpasync16_(shBase + ((AH0)<<2) + d, jb.Ah + gsrc);
            cpasync16_(shBase + ((AL0)<<2) + d, jb.Al + gsrc);
        }
        {
            int kp = tid >> 4, n4 = (tid & 15) << 2;
            size_t gsrc = (size_t)(kt2 + kp)*jb.N + n0 + n4;
            uint32_t d = (buf*1152 + kp*72 + n4) << 2;
            cpasync16_(shBase + ((BH0)<<2) + d, jb.Wh + gsrc);
            cpasync16_(shBase + ((BL0)<<2) + d, jb.Wl + gsrc);
        }
        asm volatile("cp.async.commit_group;");
    };

    load_tile(0, 0);
    int buf = 0;
    for (int t = 0; t < ntk; ++t) {
        if (t + 1 < ntk) { load_tile(buf ^ 1, t + 1); cp_wait_<1>(); }
        else cp_wait_<0>();
        __syncthreads();
        const uint32_t* Ah = smu + AH0 + buf*2560;
        const uint32_t* Al = smu + AL0 + buf*2560;
        const uint32_t* Bh = smu + BH0 + buf*1152;
        const uint32_t* Bl = smu + BL0 + buf*1152;
        #pragma unroll
        for (int ks = 0; ks < 2; ++ks) {
            int kp0 = ks << 3;
            uint32_t ah[2][4], al[2][4], bh[4][2], bl[4][2];
            #pragma unroll
            for (int mt = 0; mt < 2; ++mt) {
                int r0 = (wm + (mt << 4) + g)*20;
                ah[mt][0] = Ah[r0       + kp0+tig];
                ah[mt][1] = Ah[r0 + 160 + kp0+tig];
                ah[mt][2] = Ah[r0       + kp0+tig+4];
                ah[mt][3] = Ah[r0 + 160 + kp0+tig+4];
                al[mt][0] = Al[r0       + kp0+tig];
                al[mt][1] = Al[r0 + 160 + kp0+tig];
                al[mt][2] = Al[r0       + kp0+tig+4];
                al[mt][3] = Al[r0 + 160 + kp0+tig+4];
            }
            #pragma unroll
            for (int nt = 0; nt < 4; ++nt) {
                int cb = wn + (nt << 3) + g;
                bh[nt][0] = Bh[(kp0+tig  )*72 + cb];
                bh[nt][1] = Bh[(kp0+tig+4)*72 + cb];
                bl[nt][0] = Bl[(kp0+tig  )*72 + cb];
                bl[nt][1] = Bl[(kp0+tig+4)*72 + cb];
            }
            #pragma unroll
            for (int mt = 0; mt < 2; ++mt)
                #pragma unroll
                for (int nt = 0; nt < 4; ++nt) {
                    MMAB_(acc[mt][nt], ah[mt], bh[nt]);
                    MMAB_(acc[mt][nt], al[mt], bh[nt]);
                    MMAB_(acc[mt][nt], ah[mt], bl[nt]);
                }
        }
        __syncthreads();
        buf ^= 1;
    }

    #pragma unroll
    for (int mt = 0; mt < 2; ++mt) {
        #pragma unroll
        for (int nt = 0; nt < 4; ++nt) {
            int row = m0 + wm + (mt << 4) + g;
            int col = n0 + wn + (nt << 3) + (tig << 1);
            float v0 = acc[mt][nt][0], v1 = acc[mt][nt][1];
            float v2 = acc[mt][nt][2], v3 = acc[mt][nt][3];
            if (jb.act <= 1) {
                if (jb.bias) { float b0 = jb.bias[col], b1 = jb.bias[col+1]; v0+=b0; v1+=b1; v2+=b0; v3+=b1; }
                if (jb.act == 1) { v0=sigmoidf_(v0); v1=sigmoidf_(v1); v2=sigmoidf_(v2); v3=sigmoidf_(v3); }
                *(float2*)&jb.C[(size_t)row*jb.N + col]     = make_float2(v0, v1);
                *(float2*)&jb.C[(size_t)(row+8)*jb.N + col] = make_float2(v2, v3);
            } else {
                int j = col >> 1;
                float bm0 = v0*sigmoidf_(v0)*v1;
                float bm1 = v2*sigmoidf_(v2)*v3;
                float p0 = __shfl_xor_sync(0xffffffffu, bm0, 1);
                float p1 = __shfl_xor_sync(0xffffffffu, bm1, 1);
                if ((tig & 1) == 0) {
                    int jp = j >> 1;
                    uint32_t h, l;
                    pack2_(bm0, p0, h, l);
                    g_bm_h[(size_t)row*128 + jp] = h; g_bm_l[(size_t)row*128 + jp] = l;
                    pack2_(bm1, p1, h, l);
                    g_bm_h[(size_t)(row+8)*128 + jp] = h; g_bm_l[(size_t)(row+8)*128 + jp] = l;
                }
            }
        }
    }
}

// ------------- fused output GEMM + next-block adaln -------------------------
// CTA = 32 rows x 128 cols (full rows), grid = Tv/32 = 128, 8 warps.
// r1=ob@wo, r2=bm@wout, out=ysA*r1+ysT*r2; then per-row LN + gates for blkn.
#define OGF_AH 0
#define OGF_AL 1280
#define OGF_BH 2560
#define OGF_BL 6912
#define OGF_SMEM (11264*4)
__global__ void __launch_bounds__(256,2) outgemm_kernel(
    const uint32_t* __restrict__ Wo_h, const uint32_t* __restrict__ Wo_l,
    const uint32_t* __restrict__ Wout_h, const uint32_t* __restrict__ Wout_l,
    const float* __restrict__ ys,
    float* __restrict__ out, int blkn)
{
    int m0 = blockIdx.x << 5;
    extern __shared__ uint32_t smu[];
    uint32_t shBase = (uint32_t)__cvta_generic_to_shared(smu);
    int tid = threadIdx.x, lane = tid & 31, w = tid >> 5;
    int wm = (w & 1) << 4, wn = (w >> 1) << 5;
    int g = lane >> 2, tig = lane & 3;

    float acc1[4][4], acc2[4][4];
    #pragma unroll
    for (int nt = 0; nt < 4; ++nt)
        #pragma unroll
        for (int r = 0; r < 4; ++r) { acc1[nt][r] = 0.f; acc2[nt][r] = 0.f; }

    auto load_tile = [&](int buf, int t) {
        const uint32_t *Ash, *Asl, *Wsh, *Wsl;
        int lda, kofs;
        if (t < 4) { Ash = g_ob_h; Asl = g_ob_l; Wsh = Wo_h;   Wsl = Wo_l;   lda = 64;  kofs = t*16; }
        else       { Ash = g_bm_h; Asl = g_bm_l; Wsh = Wout_h; Wsl = Wout_l; lda = 128; kofs = (t-4)*16; }
        {   // A: 32 rows x 16 pairs = 128 float4 chunks (hi via tid<128, lo via tid>=128)
            int ch = tid & 127;
            int row = ch >> 2, kp4 = (ch & 3) << 2;
            size_t gsrc = (size_t)(m0 + row)*lda + kofs + kp4;
            uint32_t d = (buf*640 + row*20 + kp4) << 2;
            if (tid < 128) cpasync16_(shBase + (OGF_AH<<2) + d, Ash + gsrc);
            else           cpasync16_(shBase + (OGF_AL<<2) + d, Asl + gsrc);
        }
        #pragma unroll
        for (int l = 0; l < 2; ++l) {   // B: 16 rows x 128 cols, stride 136
            int id = tid + (l << 8);
            int row = id >> 5, c4 = (id & 31) << 2;
            size_t gsrc = (size_t)(kofs + row)*128 + c4;
            uint32_t d = (buf*2176 + row*136 + c4) << 2;
            cpasync16_(shBase + (OGF_BH<<2) + d, Wsh + gsrc);
            cpasync16_(shBase + (OGF_BL<<2) + d, Wsl + gsrc);
        }
        asm volatile("cp.async.commit_group;");
    };

    load_tile(0, 0);
    int buf = 0;
    for (int t = 0; t < 12; ++t) {
        if (t + 1 < 12) { load_tile(buf ^ 1, t + 1); cp_wait_<1>(); }
        else cp_wait_<0>();
        __syncthreads();
        const uint32_t* Ah = smu + OGF_AH + buf*640;
        const uint32_t* Al = smu + OGF_AL + buf*640;
        const uint32_t* Bh = smu + OGF_BH + buf*2176;
        const uint32_t* Bl = smu + OGF_BL + buf*2176;
        float (*acc)[4] = (t < 4) ? acc1 : acc2;
        #pragma unroll
        for (int ks = 0; ks < 2; ++ks) {
            int kp0 = ks << 3;
            uint32_t ah[4], al[4], bh[4][2], bl[4][2];
            int r0 = (wm + g)*20;
            ah[0] = Ah[r0       + kp0+tig];
            ah[1] = Ah[r0 + 160 + kp0+tig];
            ah[2] = Ah[r0       + kp0+tig+4];
            ah[3] = Ah[r0 + 160 + kp0+tig+4];
            al[0] = Al[r0       + kp0+tig];
            al[1] = Al[r0 + 160 + kp0+tig];
            al[2] = Al[r0       + kp0+tig+4];
            al[3] = Al[r0 + 160 + kp0+tig+4];
            #pragma unroll
            for (int nt = 0; nt < 4; ++nt) {
                int cb = wn + (nt << 3) + g;
                bh[nt][0] = Bh[(kp0+tig  )*136 + cb];
                bh[nt][1] = Bh[(kp0+tig+4)*136 + cb];
                bl[nt][0] = Bl[(kp0+tig  )*136 + cb];
                bl[nt][1] = Bl[(kp0+tig+4)*136 + cb];
            }
            #pragma unroll
            for (int nt = 0; nt < 4; ++nt) {
                MMAB_(acc[nt], ah, bh[nt]);
                MMAB_(acc[nt], al, bh[nt]);
                MMAB_(acc[nt], ah, bl[nt]);
            }
        }
        __syncthreads();
        buf ^= 1;
    }

    // epilogue: combine + write out (+ stage to smem for fused adaln)
    float* sOut = (float*)smu;   // 32 rows x stride 136
    #pragma unroll
    for (int nt = 0; nt < 4; ++nt) {
        int lr  = wm + g;
        int row = m0 + lr;
        int col = wn + (nt << 3) + (tig << 1);
        float2 yA0 = *(const float2*)&ys[(size_t)row*768 + col];
        float2 yT0 = *(const float2*)&ys[(size_t)row*768 + 128 + col];
        float2 yA1 = *(const float2*)&ys[(size_t)(row+8)*768 + col];
        float2 yT1 = *(const float2*)&ys[(size_t)(row+8)*768 + 128 + col];
        float v00 = yA0.x*acc1[nt][0] + yT0.x*acc2[nt][0];
        float v01 = yA0.y*acc1[nt][1] + yT0.y*acc2[nt][1];
        float v10 = yA1.x*acc1[nt][2] + yT1.x*acc2[nt][2];
        float v11 = yA1.y*acc1[nt][3] + yT1.y*acc2[nt][3];
        *(float2*)&out[(size_t)row*128 + col]     = make_float2(v00, v01);
        *(float2*)&out[(size_t)(row+8)*128 + col] = make_float2(v10, v11);
        if (blkn >= 0) {
            *(float2*)&sOut[lr*136 + col]     = make_float2(v00, v01);
            *(float2*)&sOut[(lr+8)*136 + col] = make_float2(v10, v11);
        }
    }
    if (blkn < 0) return;
    __syncthreads();

    // fused adaln for block blkn: warp w -> rows w*4..w*4+3
    #pragma unroll
    for (int r = 0; r < 4; ++r) {
        int lr = w*4 + r;
        int tok = m0 + lr;
        float4 av = *(const float4*)&sOut[lr*136 + lane*4];
        float s  = av.x+av.y+av.z+av.w;
        float sq = av.x*av.x+av.y*av.y+av.z*av.z+av.w*av.w;
        #pragma unroll
        for (int off = 16; off; off >>= 1) {
            s  += __shfl_xor_sync(0xffffffffu, s,  off);
            sq += __shfl_xor_sync(0xffffffffu, sq, off);
        }
        float m = s * (1.f/128.f);
        float var = sq * (1.f/128.f) - m*m;
        float rs = rsqrtf(var + 1e-5f);
        const float* yr = g_Yada + (size_t)tok*1536 + blkn*512;
        float4 yga = *(const float4*)&yr[lane*4];
        float4 ysk = *(const float4*)&yr[128 + lane*4];
        float4 ygt = *(const float4*)&yr[256 + lane*4];
        float4 yst = *(const float4*)&yr[384 + lane*4];
        float a0=(av.x-m)*rs, a1=(av.y-m)*rs, a2=(av.z-m)*rs, a3=(av.w-m)*rs;
        float ah0 = sigmoidf_(yga.x)*a0 + ysk.x;
        float ah1 = sigmoidf_(yga.y)*a1 + ysk.y;
        float ah2 = sigmoidf_(yga.z)*a2 + ysk.z;
        float ah3 = sigmoidf_(yga.w)*a3 + ysk.w;
        float tt0 = sigmoidf_(ygt.x)*a0 + yst.x;
        float tt1 = sigmoidf_(ygt.y)*a1 + yst.y;
        float tt2 = sigmoidf_(ygt.z)*a2 + yst.z;
        float tt3 = sigmoidf_(ygt.w)*a3 + yst.w;
        int o = tok*64 + lane*2;
        pack2_(ah0, ah1, g_ah_h[o],   g_ah_l[o]);
        pack2_(ah2, ah3, g_ah_h[o+1], g_ah_l[o+1]);
        pack2_(tt0, tt1, g_tt_h[o],   g_tt_l[o]);
        pack2_(tt2, tt3, g_tt_h[o+1], g_tt_l[o+1]);
    }
}

// ---------------- local attention, per-head CTA, cp.async + V prefetch ------
#define SQ_STR 36
#define SK_STR 36
#define SS_STR 132
#define OFF_SQ 0
#define OFF_SK 1152
#define OFF_SV 5760
#define OFF_SS 10368
#define ATTN_SMEM (14592*4)
__global__ void __launch_bounds__(256) attn_kernel(const float* __restrict__ zb_i)
{
    extern __shared__ float sm[];
    float* sQ = sm + OFF_SQ;
    float* sK = sm + OFF_SK;
    float* sV = sm + OFF_SV;
    float* sS = sm + OFF_SS;
    uint32_t shBase = (uint32_t)__cvta_generic_to_shared(sm);
    int j = blockIdx.x, b = blockIdx.y, h = blockIdx.z;
    int tid = threadIdx.x;
    int w = tid >> 5, lane = tid & 31;
    int k0 = 32*j - 48;
    int q0 = 32*j;
    const float scale = 0.17677669529663687f;
    const float* zbB = zb_i + (((size_t)b*32 + j) << 14) + h*4096;

    {
        int row = tid >> 3, c4 = (tid & 7) << 2;
        const float* src = &g_qkvg[((size_t)(b*Nv + q0 + row))*512 + h*32 + c4];
        cpasync16_(shBase + (OFF_SQ + row*SQ_STR + c4)*4, src);
    }
    #pragma unroll
    for (int l = 0; l < 4; ++l) {
        int id = tid + (l << 8);
        int row = id >> 3, c4 = (id & 7) << 2;
        int gk = k0 + row;
        int gkc = min(max(gk, 0), Nv-1);
        uint32_t sz = (gk >= 0 && gk < Nv) ? 16u : 0u;
        const float* src = &g_qkvg[((size_t)(b*Nv + gkc))*512 + 128 + h*32 + c4];
        cpasync16z_(shBase + (OFF_SK + row*SK_STR + c4)*4, src, sz);
    }
    asm volatile("cp.async.commit_group;");
    #pragma unroll
    for (int l = 0; l < 4; ++l) {
        int id = tid + (l << 8);
        int row = id >> 3, c4 = (id & 7) << 2;
        int gk = k0 + row;
        int gkc = min(max(gk, 0), Nv-1);
        uint32_t sz = (gk >= 0 && gk < Nv) ? 16u : 0u;
        const float* src = &g_qkvg[((size_t)(b*Nv + gkc))*512 + 256 + h*32 + c4];
        cpasync16z_(shBase + (OFF_SV + row*SK_STR + c4)*4, src, sz);
    }
    asm volatile("cp.async.commit_group;");

    cp_wait_<1>();
    __syncthreads();

    {
        int kq = w & 3, qh = (w >> 2) << 4;
        int k = kq*32 + lane;
        int gk = k0 + k;
        bool valid = (gk >= 0 && gk < Nv);
        float4 kr[8];
        #pragma unroll
        for (int jj = 0; jj < 8; ++jj)
            kr[jj] = *(const float4*)&sK[k*SK_STR + jj*4];
        #pragma unroll 4
        for (int qq = qh; qq < qh + 16; ++qq) {
            float a = 0.f;
            const float4* qp = (const float4*)&sQ[qq*SQ_STR];
            #pragma unroll
            for (int jj = 0; jj < 8; ++jj) {
                float4 qf = qp[jj];
                a += qf.x*kr[jj].x + qf.y*kr[jj].y + qf.z*kr[jj].z + qf.w*kr[jj].w;
            }
            a = a*scale + zbB[qq*128 + k];
            sS[qq*SS_STR + k] = valid ? a : -1e30f;
        }
    }
    cp_wait_<0>();
    __syncthreads();

    #pragma unroll
    for (int r = 0; r < 4; ++r) {
        int row = w*4 + r;
        float* rp = sS + row*SS_STR;
        float v0 = rp[lane], v1 = rp[lane+32], v2 = rp[lane+64], v3 = rp[lane+96];
        float mx = fmaxf(fmaxf(v0,v1), fmaxf(v2,v3));
        #pragma unroll
        for (int off = 16; off; off >>= 1) mx = fmaxf(mx, __shfl_xor_sync(0xffffffffu, mx, off));
        v0 = __expf(v0-mx); v1 = __expf(v1-mx); v2 = __expf(v2-mx); v3 = __expf(v3-mx);
        float sum = v0+v1+v2+v3;
        #pragma unroll
        for (int off = 16; off; off >>= 1) sum += __shfl_xor_sync(0xffffffffu, sum, off);
        float inv = 1.f/sum;
        rp[lane]=v0*inv; rp[lane+32]=v1*inv; rp[lane+64]=v2*inv; rp[lane+96]=v3*inv;
    }

    {
        int qq0 = w << 2;
        float acc0 = 0.f, acc1 = 0.f, acc2 = 0.f, acc3 = 0.f;
        const float* w0p = sS + (qq0+0)*SS_STR;
        const float* w1p = sS + (qq0+1)*SS_STR;
        const float* w2p = sS + (qq0+2)*SS_STR;
        const float* w3p = sS + (qq0+3)*SS_STR;
        #pragma unroll 8
        for (int k = 0; k < 128; k += 4) {
            float4 ww0 = *(const float4*)&w0p[k];
            float4 ww1 = *(const float4*)&w1p[k];
            float4 ww2 = *(const float4*)&w2p[k];
            float4 ww3 = *(const float4*)&w3p[k];
            float v0 = sV[(k+0)*SK_STR + lane];
            float v1 = sV[(k+1)*SK_STR + lane];
            float v2 = sV[(k+2)*SK_STR + lane];
            float v3 = sV[(k+3)*SK_STR + lane];
            acc0 += v0*ww0.x + v1*ww0.y + v2*ww0.z + v3*ww0.w;
            acc1 += v0*ww1.x + v1*ww1.y + v2*ww1.z + v3*ww1.w;
            acc2 += v0*ww2.x + v1*ww2.y + v2*ww2.z + v3*ww2.w;
            acc3 += v0*ww3.x + v1*ww3.y + v2*ww3.z + v3*ww3.w;
        }
        float accs[4] = {acc0, acc1, acc2, acc3};
        #pragma unroll
        for (int qi = 0; qi < 4; ++qi) {
            size_t tok = (size_t)(b*Nv + q0 + qq0 + qi);
            float gt = g_qkvg[tok*512 + 384 + h*32 + lane];
            float o = accs[qi] * sigmoidf_(gt);
            float op = __shfl_xor_sync(0xffffffffu, o, 1);
            if ((lane & 1) == 0) {
                uint32_t hh, ll;
                pack2_(o, op, hh, ll);
                int ofs = tok*64 + h*16 + (lane >> 1);
                g_ob_h[ofs] = hh; g_ob_l[ofs] = ll;
            }
        }
    }
}

// ---------------- launch ----------------
extern "C" void kernel_launch(void* const* d_in, const int* in_sizes, int n_in,
                              void* d_out, int out_size)
{
    const float* q            = (const float*)d_in[0];
    const float* c            = (const float*)d_in[1];
    const float* p            = (const float*)d_in[2];
    const float* attn_s_gamma = (const float*)d_in[3];
    const float* attn_gate_w  = (const float*)d_in[4];
    const float* attn_skip_w  = (const float*)d_in[5];
    const float* attn_wq      = (const float*)d_in[6];
    const float* attn_bq      = (const float*)d_in[7];
    const float* attn_wk      = (const float*)d_in[8];
    const float* attn_wv      = (const float*)d_in[9];
    const float* attn_lnz_g   = (const float*)d_in[10];
    const float* attn_lnz_b   = (const float*)d_in[11];
    const float* attn_wb      = (const float*)d_in[12];
    const float* attn_wgate   = (const float*)d_in[13];
    const float* attn_wo      = (const float*)d_in[14];
    const float* attn_ws_out  = (const float*)d_in[15];
    const float* attn_bs_out  = (const float*)d_in[16];
    const float* trans_s_gamma= (const float*)d_in[17];
    const float* trans_gate_w = (const float*)d_in[18];
    const float* trans_skip_w = (const float*)d_in[19];
    const float* trans_w1     = (const float*)d_in[20];
    const float* trans_w2     = (const float*)d_in[21];
    const float* trans_wout   = (const float*)d_in[22];
    const float* trans_ws_out = (const float*)d_in[23];
    const float* trans_bs_out = (const float*)d_in[24];
    float* out = (float*)d_out;

    float *p_Yada, *p_Ysig, *p_qkvg, *p_bsig, *p_bqkv, *p_zb;
    uint32_t *p_lnc_h,*p_lnc_l,*p_c_h,*p_c_l,*p_ah_h,*p_ah_l,*p_tt_h,*p_tt_l;
    uint32_t *p_Wada_h,*p_Wada_l,*p_Wsig_h,*p_Wsig_l,*p_Wqkvg_h,*p_Wqkvg_l;
    uint32_t *p_W12_h,*p_W12_l,*p_Wo_h,*p_Wo_l,*p_Wout_h,*p_Wout_l;
    cudaGetSymbolAddress((void**)&p_Yada, g_Yada);
    cudaGetSymbolAddress((void**)&p_Ysig, g_Ysig);
    cudaGetSymbolAddress((void**)&p_qkvg, g_qkvg);
    cudaGetSymbolAddress((void**)&p_bsig, g_bsig);
    cudaGetSymbolAddress((void**)&p_bqkv, g_bqkv);
    cudaGetSymbolAddress((void**)&p_zb,   g_zb);
    cudaGetSymbolAddress((void**)&p_lnc_h, g_lnc_h); cudaGetSymbolAddress((void**)&p_lnc_l, g_lnc_l);
    cudaGetSymbolAddress((void**)&p_c_h,   g_c_h);   cudaGetSymbolAddress((void**)&p_c_l,   g_c_l);
    cudaGetSymbolAddress((void**)&p_ah_h,  g_ah_h);  cudaGetSymbolAddress((void**)&p_ah_l,  g_ah_l);
    cudaGetSymbolAddress((void**)&p_tt_h,  g_tt_h);  cudaGetSymbolAddress((void**)&p_tt_l,  g_tt_l);
    cudaGetSymbolAddress((void**)&p_Wada_h, g_Wada_h); cudaGetSymbolAddress((void**)&p_Wada_l, g_Wada_l);
    cudaGetSymbolAddress((void**)&p_Wsig_h, g_Wsig_h); cudaGetSymbolAddress((void**)&p_Wsig_l, g_Wsig_l);
    cudaGetSymbolAddress((void**)&p_Wqkvg_h,g_Wqkvg_h);cudaGetSymbolAddress((void**)&p_Wqkvg_l,g_Wqkvg_l);
    cudaGetSymbolAddress((void**)&p_W12_h,  g_W12_h);  cudaGetSymbolAddress((void**)&p_W12_l,  g_W12_l);
    cudaGetSymbolAddress((void**)&p_Wo_h,   g_Wo_h);   cudaGetSymbolAddress((void**)&p_Wo_l,   g_Wo_l);
    cudaGetSymbolAddress((void**)&p_Wout_h, g_Wout_h); cudaGetSymbolAddress((void**)&p_Wout_l, g_Wout_l);

    static cudaStream_t s1 = nullptr, s2 = nullptr;
    static cudaEvent_t evRoot, evZb, evHead, evYsig, evAda0, evW12[3], evOut[3];
    if (!s1) {
        cudaStreamCreateWithFlags(&s1, cudaStreamNonBlocking);
        cudaStreamCreateWithFlags(&s2, cudaStreamNonBlocking);
        cudaEventCreateWithFlags(&evRoot, cudaEventDisableTiming);
        cudaEventCreateWithFlags(&evZb,   cudaEventDisableTiming);
        cudaEventCreateWithFlags(&evHead, cudaEventDisableTiming);
        cudaEventCreateWithFlags(&evYsig, cudaEventDisableTiming);
        cudaEventCreateWithFlags(&evAda0, cudaEventDisableTiming);
        for (int i = 0; i < 3; ++i) {
            cudaEventCreateWithFlags(&evW12[i], cudaEventDisableTiming);
            cudaEventCreateWithFlags(&evOut[i], cudaEventDisableTiming);
        }
    }

    cudaFuncSetAttribute(bgemm_kernel, cudaFuncAttributeMaxDynamicSharedMemorySize, BG_SMEM);
    cudaFuncSetAttribute(outgemm_kernel, cudaFuncAttributeMaxDynamicSharedMemorySize, OGF_SMEM);
    cudaFuncSetAttribute(attn_kernel, cudaFuncAttributeMaxDynamicSharedMemorySize, ATTN_SMEM);

    // fork s1: zb (independent of head)
    cudaEventRecord(evRoot, 0);
    cudaStreamWaitEvent(s1, evRoot, 0);
    zb_kernel<<<dim3(32, Bv), 256, 0, s1>>>(p, attn_lnz_g, attn_lnz_b, attn_wb);
    cudaEventRecord(evZb, s1);

    head_kernel<<<PACK_CTAS + Tv/8, 256>>>(
        c, attn_s_gamma, attn_gate_w, attn_skip_w,
        trans_s_gamma, trans_gate_w, trans_skip_w,
        attn_ws_out, attn_bs_out, trans_ws_out, trans_bs_out,
        attn_wq, attn_bq, attn_wk, attn_wv, attn_wgate,
        trans_w1, trans_w2, attn_wo, trans_wout);
    cudaEventRecord(evHead, 0);

    // fork s2: Ysig
    cudaStreamWaitEvent(s2, evHead, 0);
    {
        GJob js = { p_c_h, p_c_l, p_Wsig_h, p_Wsig_l, p_bsig,
                    p_Ysig, nullptr, nullptr, 64, 768, 1 };
        bgemm_kernel<<<dim3(12, 32, 1), 256, BG_SMEM, s2>>>(js, js);
    }
    cudaEventRecord(evYsig, s2);

    // main stream: Yada -> adaln(block 0 from q)
    {
        GJob ja = { p_lnc_h, p_lnc_l, p_Wada_h, p_Wada_l, nullptr,
                    p_Yada, nullptr, nullptr, 64, 1536, 0 };
        bgemm_kernel<<<dim3(24, 32, 1), 256, BG_SMEM>>>(ja, ja);
    }
    adaln_kernel<<<Tv/4, 128>>>(q, 0);
    cudaEventRecord(evAda0, 0);

    const size_t islab = (size_t)Bv*32*16384;
    for (int i = 0; i < 3; ++i) {
        // fork s1: w12 -> bm (depends on g_tt from adaln0 / fused outgemm_{i-1})
        cudaStreamWaitEvent(s1, (i == 0) ? evAda0 : evOut[i-1], 0);
        {
            GJob jw = { p_tt_h, p_tt_l, p_W12_h + (size_t)i*64*512, p_W12_l + (size_t)i*64*512,
                        nullptr, nullptr, nullptr, nullptr, 128, 512, 2 };
            bgemm_kernel<<<dim3(8, 32, 1), 256, BG_SMEM, s1>>>(jw, jw);
        }
        cudaEventRecord(evW12[i], s1);

        // main stream: qkvg -> attn
        {
            GJob jq = { p_ah_h, p_ah_l, p_Wqkvg_h + (size_t)i*64*512, p_Wqkvg_l + (size_t)i*64*512,
                        p_bqkv + i*512, p_qkvg, nullptr, nullptr, 128, 512, 0 };
            bgemm_kernel<<<dim3(8, 32, 1), 256, BG_SMEM>>>(jq, jq);
        }
        if (i == 0) cudaStreamWaitEvent(0, evZb, 0);
        attn_kernel<<<dim3(32, Bv, 4), 256, ATTN_SMEM>>>(p_zb + i*islab);

        // join: fused outgemm needs bm (s1) and Ysig (s2, first iter)
        if (i == 0) cudaStreamWaitEvent(0, evYsig, 0);
        cudaStreamWaitEvent(0, evW12[i], 0);
        outgemm_kernel<<<Tv/32, 256, OGF_SMEM>>>(
            p_Wo_h + (size_t)i*64*128, p_Wo_l + (size_t)i*64*128,
            p_Wout_h + (size_t)i*128*128, p_Wout_l + (size_t)i*128*128,
            p_Ysig + i*256, out, (i < 2) ? i + 1 : -1);
        cudaEventRecord(evOut[i], 0);
    }
}

// round 17
// speedup vs baseline: 1.1188x; 1.1188x over previous
#include <cuda_runtime.h>
#include <cuda_bf16.h>
#include <cstdint>

#define Bv 4
#define Nv 1024
#define Tv (Bv*Nv)   // 4096 tokens

__device__ __forceinline__ void gds_() {
#if __CUDA_ARCH__ >= 900
    cudaGridDependencySynchronize();
#endif
}

// ---------------- fp32 scratch ----------------
__device__ float g_Yada[Tv*1536];
__device__ float g_Ysig[Tv*768];
__device__ float g_qkvg[Tv*512];
__device__ float g_bsig[768];
__device__ float g_bqkv[3*512];
__device__ float g_zb[3*Bv*32*4*32*128];   // [i][b][j][h][qq][k] pair-bias

// ---------------- split (hi/lo bf16x2-packed) activations ----------------
__device__ uint32_t g_lnc_h[Tv*32], g_lnc_l[Tv*32];
__device__ uint32_t g_c_h[Tv*32],   g_c_l[Tv*32];
__device__ uint32_t g_ah_h[Tv*64],  g_ah_l[Tv*64];
__device__ uint32_t g_tt_h[Tv*64],  g_tt_l[Tv*64];
__device__ uint32_t g_ob_h[Tv*64],  g_ob_l[Tv*64];
__device__ uint32_t g_bm_h[Tv*128], g_bm_l[Tv*128];

// ---------------- split weights [K/2][N] ----------------
__device__ uint32_t g_Wada_h[32*1536], g_Wada_l[32*1536];
__device__ uint32_t g_Wsig_h[32*768],  g_Wsig_l[32*768];
__device__ uint32_t g_Wqkvg_h[3*64*512], g_Wqkvg_l[3*64*512];
__device__ uint32_t g_W12_h[3*64*512],   g_W12_l[3*64*512];
__device__ uint32_t g_Wo_h[3*64*128],    g_Wo_l[3*64*128];
__device__ uint32_t g_Wout_h[3*128*128], g_Wout_l[3*128*128];

__device__ __forceinline__ float sigmoidf_(float x) { return 1.f/(1.f+__expf(-x)); }
__device__ __forceinline__ void pack2_(float x0, float x1, uint32_t& h, uint32_t& l) {
    __nv_bfloat162 hh = __floats2bfloat162_rn(x0, x1);
    float r0 = x0 - __bfloat162float(hh.x);
    float r1 = x1 - __bfloat162float(hh.y);
    __nv_bfloat162 ll = __floats2bfloat162_rn(r0, r1);
    h = *reinterpret_cast<uint32_t*>(&hh);
    l = *reinterpret_cast<uint32_t*>(&ll);
}
__device__ __forceinline__ void cpasync16_(uint32_t dst, const void* src) {
    asm volatile("cp.async.ca.shared.global [%0], [%1], 16;" :: "r"(dst), "l"(src));
}
__device__ __forceinline__ void cpasync16z_(uint32_t dst, const void* src, uint32_t sz) {
    asm volatile("cp.async.ca.shared.global [%0], [%1], 16, %2;" :: "r"(dst), "l"(src), "r"(sz));
}
template<int N> __device__ __forceinline__ void cp_wait_() {
    asm volatile("cp.async.wait_group %0;" :: "n"(N));
}
#define MMAB_(acc, a, b) \
    asm volatile("mma.sync.aligned.m16n8k16.row.col.f32.bf16.bf16.f32 " \
        "{%0,%1,%2,%3}, {%4,%5,%6,%7}, {%8,%9}, {%0,%1,%2,%3};" \
        : "+f"(acc[0]), "+f"(acc[1]), "+f"(acc[2]), "+f"(acc[3]) \
        : "r"(a[0]), "r"(a[1]), "r"(a[2]), "r"(a[3]), "r"(b[0]), "r"(b[1]))

#define PACK_TOTAL (32*1536 + 32*768 + 768 + 3*64*512 + 3*512 + 3*64*512 + 3*64*128 + 3*128*128)
#define PACK_CTAS ((PACK_TOTAL + 255)/256)

// ---------------- head kernel: weight pack/split + ln(c) in one node --------
__global__ void head_kernel(
    const float* __restrict__ c,
    const float* __restrict__ attn_s_gamma, const float* __restrict__ attn_gate_w,
    const float* __restrict__ attn_skip_w,
    const float* __restrict__ trans_s_gamma, const float* __restrict__ trans_gate_w,
    const float* __restrict__ trans_skip_w,
    const float* __restrict__ attn_ws_out, const float* __restrict__ attn_bs_out,
    const float* __restrict__ trans_ws_out, const float* __restrict__ trans_bs_out,
    const float* __restrict__ wq, const float* __restrict__ bq,
    const float* __restrict__ wk, const float* __restrict__ wv,
    const float* __restrict__ wg,
    const float* __restrict__ w1, const float* __restrict__ w2,
    const float* __restrict__ wo, const float* __restrict__ wout)
{
    gds_();
    if (blockIdx.x >= PACK_CTAS) {
        int lane = threadIdx.x & 31;
        int tok = (blockIdx.x - PACK_CTAS)*8 + (threadIdx.x >> 5);
        float2 cv = *(const float2*)&c[(size_t)tok*64 + lane*2];
        float s = cv.x + cv.y, sq = cv.x*cv.x + cv.y*cv.y;
        #pragma unroll
        for (int off = 16; off; off >>= 1) {
            s  += __shfl_xor_sync(0xffffffffu, s,  off);
            sq += __shfl_xor_sync(0xffffffffu, sq, off);
        }
        float m = s * (1.f/64.f);
        float var = sq * (1.f/64.f) - m*m;
        float rs = rsqrtf(var + 1e-5f);
        pack2_((cv.x-m)*rs, (cv.y-m)*rs, g_lnc_h[tok*32+lane], g_lnc_l[tok*32+lane]);
        pack2_(cv.x, cv.y, g_c_h[tok*32+lane], g_c_l[tok*32+lane]);
        return;
    }
    int idx = blockIdx.x*blockDim.x + threadIdx.x;
    const int P0 = 32*1536;
    const int P1 = P0 + 32*768;
    const int P2 = P1 + 768;
    const int P3 = P2 + 3*64*512;
    const int P4 = P3 + 3*512;
    const int P5 = P4 + 3*64*512;
    const int P6 = P5 + 3*64*128;
    const int P7 = P6 + 3*128*128;
    if (idx < P0) {
        int kp = idx/1536, col = idx%1536;
        int i = col>>9, r = col&511, m = r>>7, o = r&127;
        const float* src = (m==0)?attn_gate_w:(m==1)?attn_skip_w:(m==2)?trans_gate_w:trans_skip_w;
        const float* gam = (m<2)?attn_s_gamma:trans_s_gamma;
        float x0 = src[(i*64+2*kp  )*128+o] * gam[i*64+2*kp];
        float x1 = src[(i*64+2*kp+1)*128+o] * gam[i*64+2*kp+1];
        pack2_(x0, x1, g_Wada_h[idx], g_Wada_l[idx]);
    } else if (idx < P1) {
        int l = idx - P0; int kp = l/768, col = l%768;
        int i = col/256, r = col%256, m = r>>7, o = r&127;
        const float* src = m ? trans_ws_out : attn_ws_out;
        pack2_(src[(i*64+2*kp)*128+o], src[(i*64+2*kp+1)*128+o], g_Wsig_h[l], g_Wsig_l[l]);
    } else if (idx < P2) {
        int col = idx - P1;
        int i = col/256, r = col%256, m = r>>7, o = r&127;
        g_bsig[col] = m ? trans_bs_out[i*128+o] : attn_bs_out[i*128+o];
    } else if (idx < P3) {
        int l = idx - P2; int i = l/(64*512); int rem = l%(64*512);
        int kp = rem>>9, col = rem&511, m = col>>7, o = col&127;
        const float* src = (m==0)?wq:(m==1)?wk:(m==2)?wv:wg;
        pack2_(src[(i*128+2*kp)*128+o], src[(i*128+2*kp+1)*128+o], g_Wqkvg_h[l], g_Wqkvg_l[l]);
    } else if (idx < P4) {
        int l = idx - P3; int i = l>>9, col = l&511;
        g_bqkv[l] = (col<128) ? bq[i*128+col] : 0.f;
    } else if (idx < P5) {
        int l = idx - P4; int i = l/(64*512); int rem = l%(64*512);
        int kp = rem>>9, col = rem&511, j = col>>1;
        const float* src = (col&1) ? w2 : w1;
        pack2_(src[(i*128+2*kp)*256+j], src[(i*128+2*kp+1)*256+j], g_W12_h[l], g_W12_l[l]);
    } else if (idx < P6) {
        int l = idx - P5; int i = l/(64*128); int rem = l%(64*128);
        int kp = rem>>7, n = rem&127;
        pack2_(wo[(i*128+2*kp)*128+n], wo[(i*128+2*kp+1)*128+n], g_Wo_h[l], g_Wo_l[l]);
    } else if (idx < P7) {
        int l = idx - P6; int i = l/(128*128); int rem = l%(128*128);
        int kp = rem>>7, n = rem&127;
        pack2_(wout[(i*256+2*kp)*128+n], wout[(i*256+2*kp+1)*128+n], g_Wout_h[l], g_Wout_l[l]);
    }
}

// ---------------- zb precompute ----------------
__global__ void __launch_bounds__(256) zb_kernel(
    const float* __restrict__ p,
    const float* __restrict__ lnz_g, const float* __restrict__ lnz_b,
    const float* __restrict__ wb)
{
    gds_();
    __shared__ float wbp[3][16][4];
    __shared__ float cst[3][4];
    int j = blockIdx.x, b = blockIdx.y;
    int tid = threadIdx.x;
    int k0 = 32*j - 48, q0 = 32*j;
    if (tid < 192) {
        int i = tid/64, r = tid%64, cc = r>>2, h = r&3;
        wbp[i][cc][h] = lnz_g[i*16+cc] * wb[i*64 + cc*4 + h];
    } else if (tid < 204) {
        int t2 = tid-192, i = t2/4, h = t2%4;
        float s = 0.f;
        for (int cc = 0; cc < 16; ++cc) s += lnz_b[i*16+cc]*wb[i*64+cc*4+h];
        cst[i][h] = s;
    }
    __syncthreads();
    size_t base0 = ((size_t)b*32 + j) << 14;
    const size_t islab = (size_t)Bv*32*16384;
    for (int pr = tid; pr < 4096; pr += 256) {
        int qq = pr >> 7, k = pr & 127;
        int gk = k0 + k;
        if (gk < 0 || gk >= Nv) {
            #pragma unroll
            for (int i = 0; i < 3; ++i)
                #pragma unroll
                for (int h = 0; h < 4; ++h)
                    g_zb[i*islab + base0 + h*4096 + qq*128 + k] = 0.f;
            continue;
        }
        const float* pp = p + (((size_t)(b*Nv + q0 + qq))*Nv + gk)*16;
        float vals[16];
        #pragma unroll
        for (int c4 = 0; c4 < 4; ++c4) {
            float4 f = ((const float4*)pp)[c4];
            vals[c4*4+0]=f.x; vals[c4*4+1]=f.y; vals[c4*4+2]=f.z; vals[c4*4+3]=f.w;
        }
        float s = 0.f, sq = 0.f;
        #pragma unroll
        for (int cc = 0; cc < 16; ++cc) { s += vals[cc]; sq += vals[cc]*vals[cc]; }
        float m = s*(1.f/16.f), var = sq*(1.f/16.f) - m*m;
        float rs = rsqrtf(var + 1e-5f);
        #pragma unroll
        for (int cc = 0; cc < 16; ++cc) vals[cc] = (vals[cc]-m)*rs;
        #pragma unroll
        for (int i = 0; i < 3; ++i) {
            #pragma unroll
            for (int h = 0; h < 4; ++h) {
                float z = cst[i][h];
                #pragma unroll
                for (int cc = 0; cc < 16; ++cc) z += vals[cc]*wbp[i][cc][h];
                g_zb[i*islab + base0 + h*4096 + qq*128 + k] = z;
            }
        }
    }
}

// ---------------- adaln: warp per token ----------------
__global__ void adaln_kernel(const float* __restrict__ a_in, int blk)
{
    gds_();
    int lane = threadIdx.x & 31;
    int tok = blockIdx.x*4 + (threadIdx.x >> 5);
    float4 av = *(const float4*)&a_in[(size_t)tok*128 + lane*4];
    float s  = av.x+av.y+av.z+av.w;
    float sq = av.x*av.x+av.y*av.y+av.z*av.z+av.w*av.w;
    #pragma unroll
    for (int off = 16; off; off >>= 1) {
        s  += __shfl_xor_sync(0xffffffffu, s,  off);
        sq += __shfl_xor_sync(0xffffffffu, sq, off);
    }
    float m = s * (1.f/128.f);
    float var = sq * (1.f/128.f) - m*m;
    float rs = rsqrtf(var + 1e-5f);
    const float* yr = g_Yada + (size_t)tok*1536 + blk*512;
    float4 yga = *(const float4*)&yr[lane*4];
    float4 ysk = *(const float4*)&yr[128 + lane*4];
    float4 ygt = *(const float4*)&yr[256 + lane*4];
    float4 yst = *(const float4*)&yr[384 + lane*4];
    float a0=(av.x-m)*rs, a1=(av.y-m)*rs, a2=(av.z-m)*rs, a3=(av.w-m)*rs;
    float ah0 = sigmoidf_(yga.x)*a0 + ysk.x;
    float ah1 = sigmoidf_(yga.y)*a1 + ysk.y;
    float ah2 = sigmoidf_(yga.z)*a2 + ysk.z;
    float ah3 = sigmoidf_(yga.w)*a3 + ysk.w;
    float tt0 = sigmoidf_(ygt.x)*a0 + yst.x;
    float tt1 = sigmoidf_(ygt.y)*a1 + yst.y;
    float tt2 = sigmoidf_(ygt.z)*a2 + yst.z;
    float tt3 = sigmoidf_(ygt.w)*a3 + yst.w;
    int o = tok*64 + lane*2;
    pack2_(ah0, ah1, g_ah_h[o],   g_ah_l[o]);
    pack2_(ah2, ah3, g_ah_h[o+1], g_ah_l[o+1]);
    pack2_(tt0, tt1, g_tt_h[o],   g_tt_l[o]);
    pack2_(tt2, tt3, g_tt_h[o+1], g_tt_l[o+1]);
}

// ------------- split-bf16 tensor GEMM, 128x64 tile, cp.async 2-stage --------
struct GJob {
    const uint32_t *Ah, *Al, *Wh, *Wl;
    const float *bias;
    float *C;
    uint32_t *Ch, *Cl;
    int K, N, act;
};
#define AH0 0
#define AL0 5120
#define BH0 10240
#define BL0 12544
#define BG_SMEM (14848*4)
__global__ void __launch_bounds__(256,2) bgemm_kernel(GJob j0, GJob j1)
{
    gds_();
    GJob jb = (blockIdx.z == 0) ? j0 : j1;
    int n0 = blockIdx.x << 6;
    if (n0 >= jb.N) return;
    int m0 = blockIdx.y << 7;
    extern __shared__ uint32_t smu[];
    uint32_t shBase = (uint32_t)__cvta_generic_to_shared(smu);

    int tid = threadIdx.x, lane = tid & 31, w = tid >> 5;
    int wm = (w & 3) << 5, wn = (w >> 2) << 5;
    int g = lane >> 2, tig = lane & 3;
    int lda = jb.K >> 1;

    float acc[2][4][4];
    #pragma unroll
    for (int mt = 0; mt < 2; ++mt)
        #pragma unroll
        for (int nt = 0; nt < 4; ++nt)
            #pragma unroll
            for (int r = 0; r < 4; ++r) acc[mt][nt][r] = 0.f;

    int ntk = jb.K >> 5;
    auto load_tile = [&](int buf, int t) {
        int kt2 = t << 4;
        #pragma unroll
        for (int l = 0; l < 2; ++l) {
            int idx = tid + (l << 8);
            int row = idx >> 2, kpb = (idx & 3) << 2;
            size_t gsrc = (size_t)(m0 + row)*lda + kt2 + kpb;
            uint32_t d = (buf*2560 + row*20 + kpb) << 2;
            cpasync16_(shBase + ((AH0)<<2) + d, jb.Ah + gsrc);
            cpasync16_(shBase + ((AL0)<<2) + d, jb.Al + gsrc);
        }
        {
            int kp = tid >> 4, n4 = (tid & 15) << 2;
            size_t gsrc = (size_t)(kt2 + kp)*jb.N + n0 + n4;
            uint32_t d = (buf*1152 + kp*72 + n4) << 2;
            cpasync16_(shBase + ((BH0)<<2) + d, jb.Wh + gsrc);
            cpasync16_(shBase + ((BL0)<<2) + d, jb.Wl + gsrc);
        }
        asm volatile("cp.async.commit_group;");
    };

    load_tile(0, 0);
    int buf = 0;
    for (int t = 0; t < ntk; ++t) {
        if (t + 1 < ntk) { load_tile(buf ^ 1, t + 1); cp_wait_<1>(); }
        else cp_wait_<0>();
        __syncthreads();
        const uint32_t* Ah = smu + AH0 + buf*2560;
        const uint32_t* Al = smu + AL0 + buf*2560;
        const uint32_t* Bh = smu + BH0 + buf*1152;
        const uint32_t* Bl = smu + BL0 + buf*1152;
        #pragma unroll
        for (int ks = 0; ks < 2; ++ks) {
            int kp0 = ks << 3;
            uint32_t ah[2][4], al[2][4], bh[4][2], bl[4][2];
            #pragma unroll
            for (int mt = 0; mt < 2; ++mt) {
                int r0 = (wm + (mt << 4) + g)*20;
                ah[mt][0] = Ah[r0       + kp0+tig];
                ah[mt][1] = Ah[r0 + 160 + kp0+tig];
                ah[mt][2] = Ah[r0       + kp0+tig+4];
                ah[mt][3] = Ah[r0 + 160 + kp0+tig+4];
                al[mt][0] = Al[r0       + kp0+tig];
                al[mt][1] = Al[r0 + 160 + kp0+tig];
                al[mt][2] = Al[r0       + kp0+tig+4];
                al[mt][3] = Al[r0 + 160 + kp0+tig+4];
            }
            #pragma unroll
            for (int nt = 0; nt < 4; ++nt) {
                int cb = wn + (nt << 3) + g;
                bh[nt][0] = Bh[(kp0+tig  )*72 + cb];
                bh[nt][1] = Bh[(kp0+tig+4)*72 + cb];
                bl[nt][0] = Bl[(kp0+tig  )*72 + cb];
                bl[nt][1] = Bl[(kp0+tig+4)*72 + cb];
            }
            #pragma unroll
            for (int mt = 0; mt < 2; ++mt)
                #pragma unroll
                for (int nt = 0; nt < 4; ++nt) {
                    MMAB_(acc[mt][nt], ah[mt], bh[nt]);
                    MMAB_(acc[mt][nt], al[mt], bh[nt]);
                    MMAB_(acc[mt][nt], ah[mt], bl[nt]);
                }
        }
        __syncthreads();
        buf ^= 1;
    }

    #pragma unroll
    for (int mt = 0; mt < 2; ++mt) {
        #pragma unroll
        for (int nt = 0; nt < 4; ++nt) {
            int row = m0 + wm + (mt << 4) + g;
            int col = n0 + wn + (nt << 3) + (tig << 1);
            float v0 = acc[mt][nt][0], v1 = acc[mt][nt][1];
            float v2 = acc[mt][nt][2], v3 = acc[mt][nt][3];
            if (jb.act <= 1) {
                if (jb.bias) { float b0 = jb.bias[col], b1 = jb.bias[col+1]; v0+=b0; v1+=b1; v2+=b0; v3+=b1; }
                if (jb.act == 1) { v0=sigmoidf_(v0); v1=sigmoidf_(v1); v2=sigmoidf_(v2); v3=sigmoidf_(v3); }
                *(float2*)&jb.C[(size_t)row*jb.N + col]     = make_float2(v0, v1);
                *(float2*)&jb.C[(size_t)(row+8)*jb.N + col] = make_float2(v2, v3);
            } else {
                int j = col >> 1;
                float bm0 = v0*sigmoidf_(v0)*v1;
                float bm1 = v2*sigmoidf_(v2)*v3;
                float p0 = __shfl_xor_sync(0xffffffffu, bm0, 1);
                float p1 = __shfl_xor_sync(0xffffffffu, bm1, 1);
                if ((tig & 1) == 0) {
                    int jp = j >> 1;
                    uint32_t h, l;
                    pack2_(bm0, p0, h, l);
                    g_bm_h[(size_t)row*128 + jp] = h; g_bm_l[(size_t)row*128 + jp] = l;
                    pack2_(bm1, p1, h, l);
                    g_bm_h[(size_t)(row+8)*128 + jp] = h; g_bm_l[(size_t)(row+8)*128 + jp] = l;
                }
            }
        }
    }
}

// ------------- fused output GEMM: r1=ob@wo, r2=bm@wout, out=ysA*r1+ysT*r2 ----
#define OG_A1H 0
#define OG_A1L 2560
#define OG_BH  5120
#define OG_BL  7424
#define OG_SMEM (9728*4)
__global__ void __launch_bounds__(256,2) outgemm_kernel(
    const uint32_t* __restrict__ Wo_h, const uint32_t* __restrict__ Wo_l,
    const uint32_t* __restrict__ Wout_h, const uint32_t* __restrict__ Wout_l,
    const float* __restrict__ ys,
    float* __restrict__ out)
{
    gds_();
    int n0 = blockIdx.x << 6, m0 = blockIdx.y << 6;
    extern __shared__ uint32_t smu[];
    uint32_t shBase = (uint32_t)__cvta_generic_to_shared(smu);
    int tid = threadIdx.x, lane = tid & 31, w = tid >> 5;
    int wm = (w & 1) << 5, wn = ((w >> 1) & 3) << 4;
    int g = lane >> 2, tig = lane & 3;

    float acc1[2][2][4], acc2[2][2][4];
    #pragma unroll
    for (int mt = 0; mt < 2; ++mt)
        #pragma unroll
        for (int nt = 0; nt < 2; ++nt)
            #pragma unroll
            for (int r = 0; r < 4; ++r) { acc1[mt][nt][r] = 0.f; acc2[mt][nt][r] = 0.f; }

    auto load_tile = [&](int buf, int t) {
        const uint32_t *Ash, *Asl, *Wsh, *Wsl;
        int lda, kofs;
        if (t < 4) { Ash = g_ob_h; Asl = g_ob_l; Wsh = Wo_h;   Wsl = Wo_l;   lda = 64;  kofs = t*16; }
        else       { Ash = g_bm_h; Asl = g_bm_l; Wsh = Wout_h; Wsl = Wout_l; lda = 128; kofs = (t-4)*16; }
        {
            int row = tid >> 2, kp4 = (tid & 3) << 2;
            size_t gsrc = (size_t)(m0 + row)*lda + kofs + kp4;
            uint32_t d = (buf*1280 + row*20 + kp4) << 2;
            cpasync16_(shBase + (OG_A1H<<2) + d, Ash + gsrc);
            cpasync16_(shBase + (OG_A1L<<2) + d, Asl + gsrc);
        }
        {
            int kp = tid >> 4, n4 = (tid & 15) << 2;
            size_t gsrc = (size_t)(kofs + kp)*128 + n0 + n4;
            uint32_t d = (buf*1152 + kp*72 + n4) << 2;
            cpasync16_(shBase + (OG_BH<<2) + d, Wsh + gsrc);
            cpasync16_(shBase + (OG_BL<<2) + d, Wsl + gsrc);
        }
        asm volatile("cp.async.commit_group;");
    };

    load_tile(0, 0);
    int buf = 0;
    for (int t = 0; t < 12; ++t) {
        if (t + 1 < 12) { load_tile(buf ^ 1, t + 1); cp_wait_<1>(); }
        else cp_wait_<0>();
        __syncthreads();
        const uint32_t* Ah = smu + OG_A1H + buf*1280;
        const uint32_t* Al = smu + OG_A1L + buf*1280;
        const uint32_t* Bh = smu + OG_BH  + buf*1152;
        const uint32_t* Bl = smu + OG_BL  + buf*1152;
        float (*acc)[2][4] = (t < 4) ? acc1 : acc2;
        #pragma unroll
        for (int ks = 0; ks < 2; ++ks) {
            int kp0 = ks << 3;
            uint32_t ah[2][4], al[2][4], bh[2][2], bl[2][2];
            #pragma unroll
            for (int mt = 0; mt < 2; ++mt) {
                int r0 = (wm + (mt << 4) + g)*20;
                ah[mt][0] = Ah[r0       + kp0+tig];
                ah[mt][1] = Ah[r0 + 160 + kp0+tig];
                ah[mt][2] = Ah[r0       + kp0+tig+4];
                ah[mt][3] = Ah[r0 + 160 + kp0+tig+4];
                al[mt][0] = Al[r0       + kp0+tig];
                al[mt][1] = Al[r0 + 160 + kp0+tig];
                al[mt][2] = Al[r0       + kp0+tig+4];
                al[mt][3] = Al[r0 + 160 + kp0+tig+4];
            }
            #pragma unroll
            for (int nt = 0; nt < 2; ++nt) {
                int cb = wn + (nt << 3) + g;
                bh[nt][0] = Bh[(kp0+tig  )*72 + cb];
                bh[nt][1] = Bh[(kp0+tig+4)*72 + cb];
                bl[nt][0] = Bl[(kp0+tig  )*72 + cb];
                bl[nt][1] = Bl[(kp0+tig+4)*72 + cb];
            }
            #pragma unroll
            for (int mt = 0; mt < 2; ++mt)
                #pragma unroll
                for (int nt = 0; nt < 2; ++nt) {
                    MMAB_(acc[mt][nt], ah[mt], bh[nt]);
                    MMAB_(acc[mt][nt], al[mt], bh[nt]);
                    MMAB_(acc[mt][nt], ah[mt], bl[nt]);
                }
        }
        __syncthreads();
        buf ^= 1;
    }

    #pragma unroll
    for (int mt = 0; mt < 2; ++mt) {
        #pragma unroll
        for (int nt = 0; nt < 2; ++nt) {
            int row = m0 + wm + (mt << 4) + g;
            int col = n0 + wn + (nt << 3) + (tig << 1);
            float2 yA0 = *(const float2*)&ys[(size_t)row*768 + col];
            float2 yT0 = *(const float2*)&ys[(size_t)row*768 + 128 + col];
            float2 yA1 = *(const float2*)&ys[(size_t)(row+8)*768 + col];
            float2 yT1 = *(const float2*)&ys[(size_t)(row+8)*768 + 128 + col];
            *(float2*)&out[(size_t)row*128 + col] = make_float2(
                yA0.x*acc1[mt][nt][0] + yT0.x*acc2[mt][nt][0],
                yA0.y*acc1[mt][nt][1] + yT0.y*acc2[mt][nt][1]);
            *(float2*)&out[(size_t)(row+8)*128 + col] = make_float2(
                yA1.x*acc1[mt][nt][2] + yT1.x*acc2[mt][nt][2],
                yA1.y*acc1[mt][nt][3] + yT1.y*acc2[mt][nt][3]);
        }
    }
}

// ---------------- local attention, per-head CTA, cp.async + V prefetch ------
#define SQ_STR 36
#define SK_STR 36
#define SS_STR 132
#define OFF_SQ 0
#define OFF_SK 1152
#define OFF_SV 5760
#define OFF_SS 10368
#define ATTN_SMEM (14592*4)
__global__ void __launch_bounds__(256) attn_kernel(const float* __restrict__ zb_i)
{
    gds_();
    extern __shared__ float sm[];
    float* sQ = sm + OFF_SQ;
    float* sK = sm + OFF_SK;
    float* sV = sm + OFF_SV;
    float* sS = sm + OFF_SS;
    uint32_t shBase = (uint32_t)__cvta_generic_to_shared(sm);
    int j = blockIdx.x, b = blockIdx.y, h = blockIdx.z;
    int tid = threadIdx.x;
    int w = tid >> 5, lane = tid & 31;
    int k0 = 32*j - 48;
    int q0 = 32*j;
    const float scale = 0.17677669529663687f;
    const float* zbB = zb_i + (((size_t)b*32 + j) << 14) + h*4096;

    {
        int row = tid >> 3, c4 = (tid & 7) << 2;
        const float* src = &g_qkvg[((size_t)(b*Nv + q0 + row))*512 + h*32 + c4];
        cpasync16_(shBase + (OFF_SQ + row*SQ_STR + c4)*4, src);
    }
    #pragma unroll
    for (int l = 0; l < 4; ++l) {
        int id = tid + (l << 8);
        int row = id >> 3, c4 = (id & 7) << 2;
        int gk = k0 + row;
        int gkc = min(max(gk, 0), Nv-1);
        uint32_t sz = (gk >= 0 && gk < Nv) ? 16u : 0u;
        const float* src = &g_qkvg[((size_t)(b*Nv + gkc))*512 + 128 + h*32 + c4];
        cpasync16z_(shBase + (OFF_SK + row*SK_STR + c4)*4, src, sz);
    }
    asm volatile("cp.async.commit_group;");
    #pragma unroll
    for (int l = 0; l < 4; ++l) {
        int id = tid + (l << 8);
        int row = id >> 3, c4 = (id & 7) << 2;
        int gk = k0 + row;
        int gkc = min(max(gk, 0), Nv-1);
        uint32_t sz = (gk >= 0 && gk < Nv) ? 16u : 0u;
        const float* src = &g_qkvg[((size_t)(b*Nv + gkc))*512 + 256 + h*32 + c4];
        cpasync16z_(shBase + (OFF_SV + row*SK_STR + c4)*4, src, sz);
    }
    asm volatile("cp.async.commit_group;");

    cp_wait_<1>();
    __syncthreads();

    {
        int kq = w & 3, qh = (w >> 2) << 4;
        int k = kq*32 + lane;
        int gk = k0 + k;
        bool valid = (gk >= 0 && gk < Nv);
        float4 kr[8];
        #pragma unroll
        for (int jj = 0; jj < 8; ++jj)
            kr[jj] = *(const float4*)&sK[k*SK_STR + jj*4];
        #pragma unroll 4
        for (int qq = qh; qq < qh + 16; ++qq) {
            float a = 0.f;
            const float4* qp = (const float4*)&sQ[qq*SQ_STR];
            #pragma unroll
            for (int jj = 0; jj < 8; ++jj) {
                float4 qf = qp[jj];
                a += qf.x*kr[jj].x + qf.y*kr[jj].y + qf.z*kr[jj].z + qf.w*kr[jj].w;
            }
            a = a*scale + zbB[qq*128 + k];
            sS[qq*SS_STR + k] = valid ? a : -1e30f;
        }
    }
    cp_wait_<0>();
    __syncthreads();

    #pragma unroll
    for (int r = 0; r < 4; ++r) {
        int row = w*4 + r;
        float* rp = sS + row*SS_STR;
        float v0 = rp[lane], v1 = rp[lane+32], v2 = rp[lane+64], v3 = rp[lane+96];
        float mx = fmaxf(fmaxf(v0,v1), fmaxf(v2,v3));
        #pragma unroll
        for (int off = 16; off; off >>= 1) mx = fmaxf(mx, __shfl_xor_sync(0xffffffffu, mx, off));
        v0 = __expf(v0-mx); v1 = __expf(v1-mx); v2 = __expf(v2-mx); v3 = __expf(v3-mx);
        float sum = v0+v1+v2+v3;
        #pragma unroll
        for (int off = 16; off; off >>= 1) sum += __shfl_xor_sync(0xffffffffu, sum, off);
        float inv = 1.f/sum;
        rp[lane]=v0*inv; rp[lane+32]=v1*inv; rp[lane+64]=v2*inv; rp[lane+96]=v3*inv;
    }

    {
        int qq0 = w << 2;
        float acc0 = 0.f, acc1 = 0.f, acc2 = 0.f, acc3 = 0.f;
        const float* w0p = sS + (qq0+0)*SS_STR;
        const float* w1p = sS + (qq0+1)*SS_STR;
        const float* w2p = sS + (qq0+2)*SS_STR;
        const float* w3p = sS + (qq0+3)*SS_STR;
        #pragma unroll 8
        for (int k = 0; k < 128; k += 4) {
            float4 ww0 = *(const float4*)&w0p[k];
            float4 ww1 = *(const float4*)&w1p[k];
            float4 ww2 = *(const float4*)&w2p[k];
            float4 ww3 = *(const float4*)&w3p[k];
            float v0 = sV[(k+0)*SK_STR + lane];
            float v1 = sV[(k+1)*SK_STR + lane];
            float v2 = sV[(k+2)*SK_STR + lane];
            float v3 = sV[(k+3)*SK_STR + lane];
            acc0 += v0*ww0.x + v1*ww0.y + v2*ww0.z + v3*ww0.w;
            acc1 += v0*ww1.x + v1*ww1.y + v2*ww1.z + v3*ww1.w;
            acc2 += v0*ww2.x + v1*ww2.y + v2*ww2.z + v3*ww2.w;
            acc3 += v0*ww3.x + v1*ww3.y + v2*ww3.z + v3*ww3.w;
        }
        float accs[4] = {acc0, acc1, acc2, acc3};
        #pragma unroll
        for (int qi = 0; qi < 4; ++qi) {
            size_t tok = (size_t)(b*Nv + q0 + qq0 + qi);
            float gt = g_qkvg[tok*512 + 384 + h*32 + lane];
            float o = accs[qi] * sigmoidf_(gt);
            float op = __shfl_xor_sync(0xffffffffu, o, 1);
            if ((lane & 1) == 0) {
                uint32_t hh, ll;
                pack2_(o, op, hh, ll);
                int ofs = tok*64 + h*16 + (lane >> 1);
                g_ob_h[ofs] = hh; g_ob_l[ofs] = ll;
            }
        }
    }
}

// ---------------- PDL launch helper ----------------
template<typename F, typename... Args>
static inline void launch_pdl(F kern, dim3 grid, dim3 block, size_t smem,
                              cudaStream_t st, Args... args)
{
    cudaLaunchConfig_t cfg = {};
    cfg.gridDim = grid; cfg.blockDim = block;
    cfg.dynamicSmemBytes = smem; cfg.stream = st;
    cudaLaunchAttribute attr[1];
    attr[0].id = cudaLaunchAttributeProgrammaticStreamSerialization;
    attr[0].val.programmaticStreamSerializationAllowed = 1;
    cfg.attrs = attr; cfg.numAttrs = 1;
    cudaLaunchKernelEx(&cfg, kern, args...);
}

// ---------------- launch ----------------
extern "C" void kernel_launch(void* const* d_in, const int* in_sizes, int n_in,
                              void* d_out, int out_size)
{
    const float* q            = (const float*)d_in[0];
    const float* c            = (const float*)d_in[1];
    const float* p            = (const float*)d_in[2];
    const float* attn_s_gamma = (const float*)d_in[3];
    const float* attn_gate_w  = (const float*)d_in[4];
    const float* attn_skip_w  = (const float*)d_in[5];
    const float* attn_wq      = (const float*)d_in[6];
    const float* attn_bq      = (const float*)d_in[7];
    const float* attn_wk      = (const float*)d_in[8];
    const float* attn_wv      = (const float*)d_in[9];
    const float* attn_lnz_g   = (const float*)d_in[10];
    const float* attn_lnz_b   = (const float*)d_in[11];
    const float* attn_wb      = (const float*)d_in[12];
    const float* attn_wgate   = (const float*)d_in[13];
    const float* attn_wo      = (const float*)d_in[14];
    const float* attn_ws_out  = (const float*)d_in[15];
    const float* attn_bs_out  = (const float*)d_in[16];
    const float* trans_s_gamma= (const float*)d_in[17];
    const float* trans_gate_w = (const float*)d_in[18];
    const float* trans_skip_w = (const float*)d_in[19];
    const float* trans_w1     = (const float*)d_in[20];
    const float* trans_w2     = (const float*)d_in[21];
    const float* trans_wout   = (const float*)d_in[22];
    const float* trans_ws_out = (const float*)d_in[23];
    const float* trans_bs_out = (const float*)d_in[24];
    float* out = (float*)d_out;

    float *p_Yada, *p_Ysig, *p_qkvg, *p_bsig, *p_bqkv, *p_zb;
    uint32_t *p_lnc_h,*p_lnc_l,*p_c_h,*p_c_l,*p_ah_h,*p_ah_l,*p_tt_h,*p_tt_l;
    uint32_t *p_Wada_h,*p_Wada_l,*p_Wsig_h,*p_Wsig_l,*p_Wqkvg_h,*p_Wqkvg_l;
    uint32_t *p_W12_h,*p_W12_l,*p_Wo_h,*p_Wo_l,*p_Wout_h,*p_Wout_l;
    cudaGetSymbolAddress((void**)&p_Yada, g_Yada);
    cudaGetSymbolAddress((void**)&p_Ysig, g_Ysig);
    cudaGetSymbolAddress((void**)&p_qkvg, g_qkvg);
    cudaGetSymbolAddress((void**)&p_bsig, g_bsig);
    cudaGetSymbolAddress((void**)&p_bqkv, g_bqkv);
    cudaGetSymbolAddress((void**)&p_zb,   g_zb);
    cudaGetSymbolAddress((void**)&p_lnc_h, g_lnc_h); cudaGetSymbolAddress((void**)&p_lnc_l, g_lnc_l);
    cudaGetSymbolAddress((void**)&p_c_h,   g_c_h);   cudaGetSymbolAddress((void**)&p_c_l,   g_c_l);
    cudaGetSymbolAddress((void**)&p_ah_h,  g_ah_h);  cudaGetSymbolAddress((void**)&p_ah_l,  g_ah_l);
    cudaGetSymbolAddress((void**)&p_tt_h,  g_tt_h);  cudaGetSymbolAddress((void**)&p_tt_l,  g_tt_l);
    cudaGetSymbolAddress((void**)&p_Wada_h, g_Wada_h); cudaGetSymbolAddress((void**)&p_Wada_l, g_Wada_l);
    cudaGetSymbolAddress((void**)&p_Wsig_h, g_Wsig_h); cudaGetSymbolAddress((void**)&p_Wsig_l, g_Wsig_l);
    cudaGetSymbolAddress((void**)&p_Wqkvg_h,g_Wqkvg_h);cudaGetSymbolAddress((void**)&p_Wqkvg_l,g_Wqkvg_l);
    cudaGetSymbolAddress((void**)&p_W12_h,  g_W12_h);  cudaGetSymbolAddress((void**)&p_W12_l,  g_W12_l);
    cudaGetSymbolAddress((void**)&p_Wo_h,   g_Wo_h);   cudaGetSymbolAddress((void**)&p_Wo_l,   g_Wo_l);
    cudaGetSymbolAddress((void**)&p_Wout_h, g_Wout_h); cudaGetSymbolAddress((void**)&p_Wout_l, g_Wout_l);

    static cudaStream_t s1 = nullptr, s2 = nullptr;
    static cudaEvent_t evRoot, evZb, evHead, evYsig, evAda[3], evW12[3];
    if (!s1) {
        cudaStreamCreateWithFlags(&s1, cudaStreamNonBlocking);
        cudaStreamCreateWithFlags(&s2, cudaStreamNonBlocking);
        cudaEventCreateWithFlags(&evRoot, cudaEventDisableTiming);
        cudaEventCreateWithFlags(&evZb,   cudaEventDisableTiming);
        cudaEventCreateWithFlags(&evHead, cudaEventDisableTiming);
        cudaEventCreateWithFlags(&evYsig, cudaEventDisableTiming);
        for (int i = 0; i < 3; ++i) {
            cudaEventCreateWithFlags(&evAda[i], cudaEventDisableTiming);
            cudaEventCreateWithFlags(&evW12[i], cudaEventDisableTiming);
        }
    }

    cudaFuncSetAttribute(bgemm_kernel, cudaFuncAttributeMaxDynamicSharedMemorySize, BG_SMEM);
    cudaFuncSetAttribute(outgemm_kernel, cudaFuncAttributeMaxDynamicSharedMemorySize, OG_SMEM);
    cudaFuncSetAttribute(attn_kernel, cudaFuncAttributeMaxDynamicSharedMemorySize, ATTN_SMEM);

    // fork s1: zb (independent of head)
    cudaEventRecord(evRoot, 0);
    cudaStreamWaitEvent(s1, evRoot, 0);
    zb_kernel<<<dim3(32, Bv), 256, 0, s1>>>(p, attn_lnz_g, attn_lnz_b, attn_wb);
    cudaEventRecord(evZb, s1);

    launch_pdl(head_kernel, dim3(PACK_CTAS + Tv/8), dim3(256), 0, (cudaStream_t)0,
        c, attn_s_gamma, attn_gate_w, attn_skip_w,
        trans_s_gamma, trans_gate_w, trans_skip_w,
        attn_ws_out, attn_bs_out, trans_ws_out, trans_bs_out,
        attn_wq, attn_bq, attn_wk, attn_wv, attn_wgate,
        trans_w1, trans_w2, attn_wo, trans_wout);
    cudaEventRecord(evHead, 0);

    // fork s2: Ysig (only needed by outgemm_0)
    cudaStreamWaitEvent(s2, evHead, 0);
    {
        GJob js = { p_c_h, p_c_l, p_Wsig_h, p_Wsig_l, p_bsig,
                    p_Ysig, nullptr, nullptr, 64, 768, 1 };
        bgemm_kernel<<<dim3(12, 32, 1), 256, BG_SMEM, s2>>>(js, js);
    }
    cudaEventRecord(evYsig, s2);

    // main stream: Yada (critical path for adaln_0)
    {
        GJob ja = { p_lnc_h, p_lnc_l, p_Wada_h, p_Wada_l, nullptr,
                    p_Yada, nullptr, nullptr, 64, 1536, 0 };
        launch_pdl(bgemm_kernel, dim3(24, 32, 1), dim3(256), (size_t)BG_SMEM,
                   (cudaStream_t)0, ja, ja);
    }

    const size_t islab = (size_t)Bv*32*16384;
    for (int i = 0; i < 3; ++i) {
        const float* a_in = (i == 0) ? q : (const float*)out;
        launch_pdl(adaln_kernel, dim3(Tv/4), dim3(128), (size_t)0, (cudaStream_t)0,
                   a_in, i);
        cudaEventRecord(evAda[i], 0);

        // fork s1: w12 -> bm (independent of qkvg/attn)
        cudaStreamWaitEvent(s1, evAda[i], 0);
        {
            GJob jw = { p_tt_h, p_tt_l, p_W12_h + (size_t)i*64*512, p_W12_l + (size_t)i*64*512,
                        nullptr, nullptr, nullptr, nullptr, 128, 512, 2 };
            bgemm_kernel<<<dim3(8, 32, 1), 256, BG_SMEM, s1>>>(jw, jw);
        }
        cudaEventRecord(evW12[i], s1);

        // main stream: qkvg -> attn
        {
            GJob jq = { p_ah_h, p_ah_l, p_Wqkvg_h + (size_t)i*64*512, p_Wqkvg_l + (size_t)i*64*512,
                        p_bqkv + i*512, p_qkvg, nullptr, nullptr, 128, 512, 0 };
            launch_pdl(bgemm_kernel, dim3(8, 32, 1), dim3(256), (size_t)BG_SMEM,
                       (cudaStream_t)0, jq, jq);
        }
        if (i == 0) cudaStreamWaitEvent(0, evZb, 0);
        launch_pdl(attn_kernel, dim3(32, Bv, 4), dim3(256), (size_t)ATTN_SMEM,
                   (cudaStream_t)0, (const float*)(p_zb + i*islab));

        // join: outgemm needs bm (s1) and Ysig (s2, first iter)
        if (i == 0) cudaStreamWaitEvent(0, evYsig, 0);
        cudaStreamWaitEvent(0, evW12[i], 0);
        launch_pdl(outgemm_kernel, dim3(2, 64), dim3(256), (size_t)OG_SMEM,
                   (cudaStream_t)0,
                   (const uint32_t*)(p_Wo_h + (size_t)i*64*128),
                   (const uint32_t*)(p_Wo_l + (size_t)i*64*128),
                   (const uint32_t*)(p_Wout_h + (size_t)i*128*128),
                   (const uint32_t*)(p_Wout_l + (size_t)i*128*128),
                   (const float*)(p_Ysig + i*256), out);
    }
}